// round 5
// baseline (speedup 1.0000x reference)
#include <cuda_runtime.h>
#include <math.h>

// Shapes fixed by the reference:
//  B=16,T=32 -> BT=512 ; NP=8, NG=4, J=14, H=256
#define BT      512
#define NPRED   8
#define NGT     4
#define NJ      14
#define NPERM   1680                 // P(8,4)
#define HEAT_N  (512 * 256 * 256)    // 33,554,432 floats
#define N4      (HEAT_N / 4)         // 8,388,608 float4
#define NBLK    1024
#define NMATCH  512
#define WM      7                    // heat-work weight for match blocks
#define WH      8                    // heat-work weight for heat-only blocks
#define TOTW    (NMATCH * WM + (NBLK - NMATCH) * WH)   // 7680

#define INV_HEAT (1.0f / (float)HEAT_N)
#define INV_BT   (1.0f / 512.0f)
#define INV_POSE (1.0f / (512.0f * 8.0f * 14.0f))

__device__ float        g_part[NBLK];   // per-block heat partial
__device__ float        g_match[BT];    // per-(b,t) combined match contribution
__device__ unsigned int g_count;        // completion counter (self-resetting)

// Monotone float->uint map: equal floats -> equal keys, order preserved.
__device__ __forceinline__ unsigned f2ord(float v) {
    unsigned u = __float_as_uint(v);
    return (u & 0x80000000u) ? ~u : (u | 0x80000000u);
}

__device__ __forceinline__ unsigned long long umin64(unsigned long long a,
                                                     unsigned long long b) {
    return a < b ? a : b;
}

// Lexicographic rank -> k-permutation of range(8), k=4. Register-only
// (bitmask + d-th-set-bit), matches itertools.permutations order.
__device__ __forceinline__ void decode_perm(int r, int* p) {
    const int divs[4] = {210, 30, 5, 1};
    unsigned mask = 0xFFu;
#pragma unroll
    for (int k = 0; k < 4; k++) {
        int d = r / divs[k];
        r -= d * divs[k];
        unsigned m = mask;
#pragma unroll
        for (int q = 0; q < 7; q++)
            if (q < d) m &= (m - 1);   // clear d lowest set bits
        int idx = __ffs(m) - 1;
        mask &= ~(1u << idx);
        p[k] = idx;
    }
}

__global__ void __launch_bounds__(256, 7)
k_fused(const float4* __restrict__ ha,   // hor_heatmap as float4
        const float4* __restrict__ hb,   // gt_heatmap  as float4
        const float* __restrict__ po_all,   // hor_offset  (BT,8,2)
        const float* __restrict__ ps_all,   // hor_bsize   (BT,8,4)
        const float* __restrict__ pc_all,   // hor_center  (BT,8,2)
        const float* __restrict__ sc_all,   // scores      (BT,8)
        const float* __restrict__ pp_all,   // x_pose3d    (BT,8,14,3)
        const float* __restrict__ gs_all,   // gt_boxes_wh (BT,4,4)
        const float* __restrict__ go_all,   // gt_offset   (BT,4,2)
        const float* __restrict__ gc_all,   // gt_center   (BT,4,2)
        const float* __restrict__ gp_all,   // gt_pose3d   (BT,4,14,3)
        float* __restrict__ out)
{
    const int bid = blockIdx.x;
    const int t   = threadIdx.x;

    __shared__ float Cb[NPRED][NGT];
    __shared__ float Cp[NPRED][NGT];
    __shared__ unsigned long long wmin[2][8];
    __shared__ int   s_pb[4], s_pq[4];
    __shared__ float sred[256];
    __shared__ bool  isLast;

    // ------------------------------------------------------------------
    // Phase 1 (blocks 0..511): exhaustive Hungarian match for bt = bid.
    // ------------------------------------------------------------------
    if (bid < NMATCH) {
        const int bt = bid;
        const float* pc = pc_all + bt * 16;
        const float* gc = gc_all + bt * 8;
        const float* sc = sc_all + bt * 8;
        const float* pp = pp_all + bt * NPRED * 42;
        const float* gp = gp_all + bt * NGT * 42;

        // Cost matrices: 32 threads, one (i,j) each.
        if (t < 32) {
            int i = t >> 2, j = t & 3;
            float dx = pc[2 * i]     - gc[2 * j];
            float dy = pc[2 * i + 1] - gc[2 * j + 1];
            Cb[i][j] = sqrtf(dx * dx + dy * dy) - sc[i];
            float s = 0.f;
            const float* pi = pp + i * 42;
            const float* gj = gp + j * 42;
#pragma unroll
            for (int k = 0; k < 42; k++) {
                float d = pi[k] - gj[k];
                s += d * d;
            }
            Cp[i][j] = sqrtf(s);
        }
        __syncthreads();

        // Sweep all 1680 ranks; min over (orderedFloat, rank) keys gives
        // exact first-min argmin semantics.
        unsigned long long kb = ~0ull, kp = ~0ull;
        for (int r = t; r < NPERM; r += 256) {
            int p[4];
            decode_perm(r, p);
            float tb = Cb[p[0]][0] + Cb[p[1]][1] + Cb[p[2]][2] + Cb[p[3]][3];
            float tp = Cp[p[0]][0] + Cp[p[1]][1] + Cp[p[2]][2] + Cp[p[3]][3];
            kb = umin64(kb, ((unsigned long long)f2ord(tb) << 32) | (unsigned)r);
            kp = umin64(kp, ((unsigned long long)f2ord(tp) << 32) | (unsigned)r);
        }
#pragma unroll
        for (int o = 16; o > 0; o >>= 1) {
            kb = umin64(kb, __shfl_down_sync(0xffffffffu, kb, o));
            kp = umin64(kp, __shfl_down_sync(0xffffffffu, kp, o));
        }
        if ((t & 31) == 0) { wmin[0][t >> 5] = kb; wmin[1][t >> 5] = kp; }
        __syncthreads();
        if (t == 0) {
            unsigned long long b = wmin[0][0], q = wmin[1][0];
#pragma unroll
            for (int w = 1; w < 8; w++) {
                b = umin64(b, wmin[0][w]);
                q = umin64(q, wmin[1][w]);
            }
            int pb[4], pq[4];
            decode_perm((int)(b & 0xFFFFFFFFu), pb);
            decode_perm((int)(q & 0xFFFFFFFFu), pq);
#pragma unroll
            for (int j = 0; j < 4; j++) { s_pb[j] = pb[j]; s_pq[j] = pq[j]; }
        }
        __syncthreads();

        // Tail losses: warp 0, parallel over terms, shuffle-sum (fixed order).
        if (t < 32) {
            float pose_acc = 0.f, box_acc = 0.f;
            // pose: 4*42 = 168 squared diffs
            for (int idx = t; idx < 168; idx += 32) {
                int j = idx / 42, k = idx - j * 42;
                float d = pp[s_pq[j] * 42 + k] - gp[idx];
                pose_acc += d * d;
            }
            // offset (0.5*L1 over 2) + size (0.25*L1 over 4): 24 terms
            if (t < 24) {
                int j = t / 6, w = t - j * 6;
                int i = s_pb[j];
                if (w < 2) {
                    box_acc = 0.5f * fabsf(po_all[bt * 16 + i * 2 + w] -
                                           go_all[bt * 8  + j * 2 + w]);
                } else {
                    int k = w - 2;
                    box_acc = 0.25f * fabsf(ps_all[bt * 32 + i * 4 + k] -
                                            gs_all[bt * 16 + j * 4 + k]);
                }
            }
            float v = pose_acc * INV_POSE + box_acc * INV_BT;
#pragma unroll
            for (int o = 16; o > 0; o >>= 1)
                v += __shfl_down_sync(0xffffffffu, v, o);
            if (t == 0) g_match[bt] = v;
        }
        __syncthreads();
    }

    // ------------------------------------------------------------------
    // Phase 2 (all blocks): heatmap MSE over a statically skewed range.
    // Simple 2-load loop (low MLP_p1 — avoids cross-CTA L1tex-queue
    // contention per the B300 spread model); plain LDG (R1 hit the
    // 6.27 TB/s ceiling with exactly this shape).
    // ------------------------------------------------------------------
    {
        long long cw0 = (bid < NMATCH)
                            ? (long long)bid * WM
                            : (long long)NMATCH * WM + (long long)(bid - NMATCH) * WH;
        long long cw1 = cw0 + ((bid < NMATCH) ? WM : WH);
        long long s = cw0 * (long long)N4 / TOTW;
        long long e = cw1 * (long long)N4 / TOTW;

        float acc = 0.f;
        for (long long i = s + t; i < e; i += 256) {
            float4 x = ha[i];
            float4 y = hb[i];
            float dx = x.x - y.x, dy = x.y - y.y, dz = x.z - y.z, dw = x.w - y.w;
            acc += dx * dx + dy * dy + dz * dz + dw * dw;
        }

        sred[t] = acc;
        __syncthreads();
#pragma unroll
        for (int o = 128; o > 0; o >>= 1) {
            if (t < o) sred[t] += sred[t + o];
            __syncthreads();
        }
        if (t == 0) g_part[bid] = sred[0];
    }

    // ------------------------------------------------------------------
    // Phase 3: last block to arrive does the final combine
    // (classic threadFenceReduction: writer fence + atomic ticket).
    // ------------------------------------------------------------------
    if (t == 0) {
        __threadfence();
        unsigned old = atomicAdd(&g_count, 1u);
        isLast = (old == NBLK - 1);
    }
    __syncthreads();

    if (isLast) {
        __threadfence();
        float v = 0.f;
        for (int i = t; i < NBLK; i += 256) v += g_part[i] * INV_HEAT;
        for (int i = t; i < BT;   i += 256) v += g_match[i];
        __syncthreads();            // sred reuse barrier
        sred[t] = v;
        __syncthreads();
#pragma unroll
        for (int o = 128; o > 0; o >>= 1) {
            if (t < o) sred[t] += sred[t + o];
            __syncthreads();
        }
        if (t == 0) {
            out[0]  = sred[0];
            g_count = 0;            // reset for next graph replay
        }
    }
}

extern "C" void kernel_launch(void* const* d_in, const int* in_sizes, int n_in,
                              void* d_out, int out_size) {
    const float* hor_heatmap = (const float*)d_in[0];
    const float* hor_offset  = (const float*)d_in[1];
    const float* hor_bsize   = (const float*)d_in[2];
    const float* hor_center  = (const float*)d_in[3];
    const float* scores      = (const float*)d_in[4];
    const float* x_pose3d    = (const float*)d_in[5];
    const float* gt_heatmap  = (const float*)d_in[6];
    const float* gt_boxes_wh = (const float*)d_in[7];
    const float* gt_offset   = (const float*)d_in[8];
    const float* gt_center   = (const float*)d_in[9];
    const float* gt_pose3d   = (const float*)d_in[10];

    k_fused<<<NBLK, 256>>>((const float4*)hor_heatmap, (const float4*)gt_heatmap,
                           hor_offset, hor_bsize, hor_center, scores, x_pose3d,
                           gt_boxes_wh, gt_offset, gt_center, gt_pose3d,
                           (float*)d_out);
}